// round 7
// baseline (speedup 1.0000x reference)
#include <cuda_runtime.h>
#include <cstdint>
#include <math.h>

#define H 128
#define AP 132           // activation stride (floats) -> conflict-free A-frag LDS
#define NODES 32         // nodes per CTA
#define GPC 4            // graphs per CTA
#define NT 128

// shared layout (float offsets) -- activations only, weights come from gmem/L2
#define OFF_X0 0
#define OFF_A  (OFF_X0 + NODES*AP)     // 4224
#define OFF_B  (OFF_A  + NODES*AP)     // 8448
#define OFF_G  (OFF_B  + NODES*AP)     // 12672
#define OFF_POS (OFF_G + GPC*AP)       // 13200
#define OFF_D  (OFF_POS + NODES*2)     // 13264
#define OFF_INT (OFF_D + NODES*8)      // 13520
#define SMEM_FLOATS (OFF_INT + 80)     // 13600 floats = 54400 B -> 4 CTAs/SM

__device__ __forceinline__ uint32_t f2tf32(float f) {
    uint32_t r;
    asm("cvt.rna.tf32.f32 %0, %1;" : "=r"(r) : "f"(f));
    return r;
}
// split fp32 -> (hi, lo); lo passed as raw fp32 bits (MMA truncates, error ~2^-23)
__device__ __forceinline__ void tf32_split(float f, uint32_t& hi, uint32_t& lo) {
    hi = f2tf32(f);
    lo = __float_as_uint(f - __uint_as_float(hi));
}

__device__ __forceinline__ void mma_tf32(float* c, const uint32_t* a, const uint32_t* b)
{
    asm volatile(
        "mma.sync.aligned.m16n8k8.row.col.f32.tf32.tf32.f32 "
        "{%0,%1,%2,%3}, {%4,%5,%6,%7}, {%8,%9}, {%0,%1,%2,%3};"
        : "+f"(c[0]), "+f"(c[1]), "+f"(c[2]), "+f"(c[3])
        : "r"(a[0]), "r"(a[1]), "r"(a[2]), "r"(a[3]), "r"(b[0]), "r"(b[1]));
}

// acc += X[32x128] @ W[128x128]; X fp32 in smem (stride AP), W fp32 in GMEM row-major.
// 4 warps: warp w covers output cols w*32..w*32+31 (4 n-tiles), rows 0..31 (2 m-tiles).
// 3xTF32 compensated (hi*hi + lo*hi + hi*lo).
__device__ __forceinline__ void gemm_acc(const float* __restrict__ X,
                                         const float* __restrict__ gW,
                                         float acc[2][4][4])
{
    const int lane = threadIdx.x & 31;
    const int warp = threadIdx.x >> 5;
    const int n0 = warp * 32;
    const int g = lane >> 2, tig = lane & 3;

#pragma unroll 2
    for (int k0 = 0; k0 < H; k0 += 8) {
        // B-frags straight from gmem (L1/L2-hot: same weights for every CTA)
        float bw[4][2];
#pragma unroll
        for (int nt = 0; nt < 4; ++nt) {
            int c = n0 + nt * 8 + g;
            bw[nt][0] = __ldg(&gW[(k0 + tig) * H + c]);
            bw[nt][1] = __ldg(&gW[(k0 + tig + 4) * H + c]);
        }
        // A-frags from shared (conflict-free at stride AP=132)
        uint32_t ah[2][4], al[2][4];
#pragma unroll
        for (int mt = 0; mt < 2; ++mt) {
            int r = mt * 16 + g;
            tf32_split(X[r * AP + k0 + tig],           ah[mt][0], al[mt][0]);
            tf32_split(X[(r + 8) * AP + k0 + tig],     ah[mt][1], al[mt][1]);
            tf32_split(X[r * AP + k0 + tig + 4],       ah[mt][2], al[mt][2]);
            tf32_split(X[(r + 8) * AP + k0 + tig + 4], ah[mt][3], al[mt][3]);
        }
        uint32_t bh[4][2], bl[4][2];
#pragma unroll
        for (int nt = 0; nt < 4; ++nt) {
            tf32_split(bw[nt][0], bh[nt][0], bl[nt][0]);
            tf32_split(bw[nt][1], bh[nt][1], bl[nt][1]);
        }
#pragma unroll
        for (int mt = 0; mt < 2; ++mt)
#pragma unroll
            for (int nt = 0; nt < 4; ++nt) {
                mma_tf32(acc[mt][nt], ah[mt], bh[nt]);
                mma_tf32(acc[mt][nt], al[mt], bh[nt]);
                mma_tf32(acc[mt][nt], ah[mt], bl[nt]);
            }
    }
}

__device__ __forceinline__ void gemm_epi(float acc[2][4][4], float* __restrict__ C,
                                         const float* __restrict__ gbias, float biasScale,
                                         bool doRelu)
{
    const int lane = threadIdx.x & 31;
    const int warp = threadIdx.x >> 5;
    const int n0 = warp * 32;
    const int g = lane >> 2, tig = lane & 3;
#pragma unroll
    for (int mt = 0; mt < 2; ++mt) {
#pragma unroll
        for (int nt = 0; nt < 4; ++nt) {
            int r = mt * 16 + g;
            int c = n0 + nt * 8 + 2 * tig;
#pragma unroll
            for (int h = 0; h < 2; ++h) {
                int rr = r + h * 8;
#pragma unroll
                for (int q = 0; q < 2; ++q) {
                    float v = acc[mt][nt][h * 2 + q];
                    if (gbias) v += biasScale * __ldg(&gbias[c + q]);
                    if (doRelu) v = fmaxf(v, 0.f);
                    C[rr * AP + c + q] = v;
                }
            }
        }
    }
}

#define ACC_ZERO(acc) do {                                             \
    _Pragma("unroll")                                                  \
    for (int _m = 0; _m < 2; ++_m)                                     \
        _Pragma("unroll")                                              \
        for (int _n = 0; _n < 4; ++_n)                                 \
            _Pragma("unroll")                                          \
            for (int _i = 0; _i < 4; ++_i) acc[_m][_n][_i] = 0.f;      \
} while (0)

__global__ __launch_bounds__(NT, 4) void prettyrnn_kernel(
    const int* __restrict__ anchors, const int* __restrict__ n_jumps,
    const float* __restrict__ positions, const int* __restrict__ colors,
    const int* __restrict__ markers,
    const float* __restrict__ pre_W1, const float* __restrict__ pre_b1,
    const float* __restrict__ pre_W2, const float* __restrict__ pre_b2,
    const float* __restrict__ msg_W1, const float* __restrict__ msg_b1,
    const float* __restrict__ msg_W2, const float* __restrict__ msg_b2,
    const float* __restrict__ post_W1, const float* __restrict__ post_b1,
    const float* __restrict__ post_W2, const float* __restrict__ post_b2,
    const float* __restrict__ out_W1, const float* __restrict__ out_b1,
    const float* __restrict__ out_W2, const float* __restrict__ out_b2,
    float* __restrict__ out)
{
    extern __shared__ float sm[];
    float* sX0 = sm + OFF_X0;
    float* sA  = sm + OFF_A;
    float* sB  = sm + OFF_B;
    float* sG  = sm + OFF_G;
    float* sPos = sm + OFF_POS;
    float* sD  = sm + OFF_D;
    int* sCol = (int*)(sm + OFF_INT);
    int* sMrk = sCol + NODES;
    int* sAnc = sMrk + NODES;
    int* sJmp = sAnc + GPC;

    const int tid = threadIdx.x;
    const int nodeBase = blockIdx.x * NODES;
    const int graphBase = blockIdx.x * GPC;
    const int tx = tid & 15;
    const int ty = tid >> 4;
    const int r0 = ty * 4;          // 8 ty * 4 rows = 32 rows
    const int c0 = tx * 8;          // 16 tx * 8 cols = 128 cols

    // ---- phase 0: per-node / per-graph inputs ----
    if (tid < NODES) {
        sCol[tid] = colors[nodeBase + tid];
        sMrk[tid] = markers[nodeBase + tid];
        sPos[2 * tid]     = positions[2 * (nodeBase + tid)];
        sPos[2 * tid + 1] = positions[2 * (nodeBase + tid) + 1];
    }
    if (tid >= NODES && tid < NODES + GPC) {
        int g = tid - NODES;
        sAnc[g] = anchors[graphBase + g];
        sJmp[g] = n_jumps[graphBase + g];
    }
    __syncthreads();

    // ---- distances ----
    for (int idx = tid; idx < NODES * 8; idx += NT) {
        int n = idx >> 3, jj = idx & 7;
        int j = (n & ~7) + jj;
        float dx = sPos[2 * n]     - sPos[2 * j];
        float dy = sPos[2 * n + 1] - sPos[2 * j + 1];
        sD[idx] = sqrtf(dx * dx + dy * dy);
    }

    // ---- pre layer 1 (one-hot gather from gmem rows) -> sA (fp32, relu) ----
    {
#pragma unroll
        for (int i = 0; i < 4; ++i) {
            int n = r0 + i;
            int g = n >> 3;
            float px = sPos[2 * n], py = sPos[2 * n + 1];
            const float* rw0 = pre_W1;
            const float* rw1 = pre_W1 + H;
            const float* rc = pre_W1 + (2 + sCol[n]) * H;
            const float* rm = pre_W1 + (10 + (sMrk[n] - 8)) * H;
            const float* ra = pre_W1 + (18 + sAnc[g]) * H;
            const float* rj = pre_W1 + (34 + sJmp[g]) * H;
#pragma unroll
            for (int c = 0; c < 8; ++c) {
                int k = c0 + c;
                float v = __ldg(&rc[k]) + __ldg(&rm[k]) + __ldg(&ra[k])
                        + __ldg(&rj[k]) + __ldg(&pre_b1[k]);
                v = fmaf(px, __ldg(&rw0[k]), fmaf(py, __ldg(&rw1[k]), v));
                sA[n * AP + k] = fmaxf(v, 0.f);
            }
        }
    }
    __syncthreads();

    // ---- pre layer 2 (linear): x0 = h1 @ pre_W2 + b2 -> sX0 ----
    {
        float acc[2][4][4]; ACC_ZERO(acc);
        gemm_acc(sA, pre_W2, acc);
        gemm_epi(acc, sX0, pre_b2, 1.f, false);
    }
    __syncthreads();

    // ---- A = x0 @ msg_W1[0:128] -> sA ; B = x0 @ msg_W1[128:256] -> sB (no sync between) ----
    {
        float acc[2][4][4]; ACC_ZERO(acc);
        gemm_acc(sX0, msg_W1, acc);
        gemm_epi(acc, sA, nullptr, 0.f, false);
    }
    {
        float acc[2][4][4]; ACC_ZERO(acc);
        gemm_acc(sX0, msg_W1 + H * H, acc);
        gemm_epi(acc, sB, nullptr, 0.f, false);
    }
    __syncthreads();

    // ---- edge aggregation: s[n] = sum_{j!=n} relu(A[n]+B[j]+d*w1d+b1) -> sA ----
    {
        const float* w1d = msg_W1 + 2 * H * H;
        float wv[8], bv[8];
#pragma unroll
        for (int c = 0; c < 8; ++c) {
            wv[c] = __ldg(&w1d[c0 + c]);
            bv[c] = __ldg(&msg_b1[c0 + c]);
        }
#pragma unroll
        for (int i = 0; i < 4; ++i) {
            int n = r0 + i, nb = n & ~7, nloc = n & 7;
            float a[8];
            {
                float4 a0 = *(const float4*)&sA[n * AP + c0];
                float4 a1 = *(const float4*)&sA[n * AP + c0 + 4];
                a[0]=a0.x; a[1]=a0.y; a[2]=a0.z; a[3]=a0.w; a[4]=a1.x; a[5]=a1.y; a[6]=a1.z; a[7]=a1.w;
            }
            float s[8] = {0,0,0,0,0,0,0,0};
#pragma unroll
            for (int jj = 0; jj < 8; ++jj) {
                if (jj == nloc) continue;
                float d = sD[n * 8 + jj];
                const float* bp = sB + (nb + jj) * AP + c0;
                float4 b0 = *(const float4*)bp;
                float4 b1 = *(const float4*)(bp + 4);
                float bb[8] = {b0.x, b0.y, b0.z, b0.w, b1.x, b1.y, b1.z, b1.w};
#pragma unroll
                for (int c = 0; c < 8; ++c) {
                    float t = a[c] + bb[c] + fmaf(d, wv[c], bv[c]);
                    s[c] += fmaxf(t, 0.f);
                }
            }
            *(float4*)&sA[n * AP + c0]     = make_float4(s[0], s[1], s[2], s[3]);
            *(float4*)&sA[n * AP + c0 + 4] = make_float4(s[4], s[5], s[6], s[7]);
        }
    }
    __syncthreads();

    // ---- upd = s @ msg_W2 + 7*msg_b2 -> sB ----
    {
        float acc[2][4][4]; ACC_ZERO(acc);
        gemm_acc(sA, msg_W2, acc);
        gemm_epi(acc, sB, msg_b2, 7.f, false);
    }
    __syncthreads();

    // ---- post layer 1 (fused 2K gemm, acc register-resident): h = relu(upd@P1a + x0@P1b + b1) -> sA ----
    {
        float acc[2][4][4]; ACC_ZERO(acc);
        gemm_acc(sB,  post_W1, acc);
        gemm_acc(sX0, post_W1 + H * H, acc);
        gemm_epi(acc, sA, post_b1, 1.f, true);
    }
    __syncthreads();

    // ---- post layer 2: x = h @ post_W2 + b2 -> sB ----
    {
        float acc[2][4][4]; ACC_ZERO(acc);
        gemm_acc(sA, post_W2, acc);
        gemm_epi(acc, sB, post_b2, 1.f, false);
    }
    __syncthreads();

    // ---- graph sum -> sG ----
    for (int idx = tid; idx < GPC * H; idx += NT) {
        int g = idx >> 7, k = idx & (H - 1);
        float s = 0.f;
#pragma unroll
        for (int i = 0; i < 8; ++i) s += sB[(g * 8 + i) * AP + k];
        sG[g * AP + k] = s;
    }
    __syncthreads();

    // ---- out layer 1 (SIMT, weights direct from gmem; col k=tid fixed per thread) ----
    {
        float s0 = __ldg(&out_b1[tid]);
        float s1 = s0, s2 = s0, s3 = s0;
#pragma unroll 4
        for (int kk = 0; kk < H; ++kk) {
            float w = __ldg(&out_W1[kk * H + tid]);
            s0 = fmaf(sG[0 * AP + kk], w, s0);
            s1 = fmaf(sG[1 * AP + kk], w, s1);
            s2 = fmaf(sG[2 * AP + kk], w, s2);
            s3 = fmaf(sG[3 * AP + kk], w, s3);
        }
        sB[0 * AP + tid] = fmaxf(s0, 0.f);
        sB[1 * AP + tid] = fmaxf(s1, 0.f);
        sB[2 * AP + tid] = fmaxf(s2, 0.f);
        sB[3 * AP + tid] = fmaxf(s3, 0.f);
    }
    __syncthreads();

    // ---- out layer 2 (SIMT): logits -> gmem ----
    if (tid < GPC * 16) {
        int g = tid >> 4, o = tid & 15;
        float s = __ldg(&out_b2[o]);
#pragma unroll 8
        for (int k = 0; k < H; ++k)
            s = fmaf(sB[g * AP + k], __ldg(&out_W2[k * 16 + o]), s);
        out[(graphBase + g) * 16 + o] = s;
    }
}

extern "C" void kernel_launch(void* const* d_in, const int* in_sizes, int n_in,
                              void* d_out, int out_size)
{
    const int*   anchors   = (const int*)d_in[0];
    const int*   n_jumps   = (const int*)d_in[1];
    const float* positions = (const float*)d_in[2];
    const int*   colors    = (const int*)d_in[3];
    const int*   markers   = (const int*)d_in[4];
    const float* pre_W1  = (const float*)d_in[5];
    const float* pre_b1  = (const float*)d_in[6];
    const float* pre_W2  = (const float*)d_in[7];
    const float* pre_b2  = (const float*)d_in[8];
    const float* msg_W1  = (const float*)d_in[9];
    const float* msg_b1  = (const float*)d_in[10];
    const float* msg_W2  = (const float*)d_in[11];
    const float* msg_b2  = (const float*)d_in[12];
    const float* post_W1 = (const float*)d_in[13];
    const float* post_b1 = (const float*)d_in[14];
    const float* post_W2 = (const float*)d_in[15];
    const float* post_b2 = (const float*)d_in[16];
    const float* out_W1  = (const float*)d_in[17];
    const float* out_b1  = (const float*)d_in[18];
    const float* out_W2  = (const float*)d_in[19];
    const float* out_b2  = (const float*)d_in[20];

    int bs = in_sizes[0];
    int blocks = bs / GPC;
    size_t smemBytes = SMEM_FLOATS * sizeof(float);
    cudaFuncSetAttribute(prettyrnn_kernel,
                         cudaFuncAttributeMaxDynamicSharedMemorySize, (int)smemBytes);
    prettyrnn_kernel<<<blocks, NT, smemBytes>>>(
        anchors, n_jumps, positions, colors, markers,
        pre_W1, pre_b1, pre_W2, pre_b2,
        msg_W1, msg_b1, msg_W2, msg_b2,
        post_W1, post_b1, post_W2, post_b2,
        out_W1, out_b1, out_W2, out_b2,
        (float*)d_out);
}

// round 8
// speedup vs baseline: 2.5244x; 2.5244x over previous
#include <cuda_runtime.h>
#include <cuda_bf16.h>
#include <cstdint>
#include <math.h>

#define H 128
#define AP 132           // activation stride (floats)
#define NODES 32         // nodes per CTA
#define GPC 4            // graphs per CTA
#define NT 128

// shared layout (float offsets) -- activations only
#define OFF_X0 0
#define OFF_A  (OFF_X0 + NODES*AP)     // 4224
#define OFF_B  (OFF_A  + NODES*AP)     // 8448
#define OFF_G  (OFF_B  + NODES*AP)     // 12672
#define OFF_POS (OFF_G + GPC*AP)       // 13200
#define OFF_D  (OFF_POS + NODES*2)     // 13264
#define OFF_INT (OFF_D + NODES*8)      // 13520
#define SMEM_FLOATS (OFF_INT + 80)     // 13600 floats = 54400 B

// packed weights: 7 matrices x [kc(8)][c(128)][t(4)] entries of uint4 {bh01, bh89, bl01, bl89}
#define NMAT 7
#define MAT_ENTRIES (8 * 128 * 4)      // 4096 uint4 per matrix
__device__ uint4 g_Wpk[NMAT * MAT_ENTRIES];   // 448 KB

// ---- bf16 helpers ----
__device__ __forceinline__ uint32_t bpack(float lo, float hi) {   // lo -> bits[0:16), hi -> bits[16:32)
    uint32_t r;
    asm("cvt.rn.bf16x2.f32 %0, %1, %2;" : "=r"(r) : "f"(hi), "f"(lo));
    return r;
}
__device__ __forceinline__ float bf_lo(uint32_t p) { return __uint_as_float(p << 16); }
__device__ __forceinline__ float bf_hi(uint32_t p) { return __uint_as_float(p & 0xffff0000u); }

// split a float2 (consecutive k) into packed bf16 hi-pair and lo-pair
__device__ __forceinline__ void bsplit2(float2 v, uint32_t& h, uint32_t& l) {
    h = bpack(v.x, v.y);
    l = bpack(v.x - bf_lo(h), v.y - bf_hi(h));
}

// ---- prep kernel: pack weight matrices into mma-B-fragment order, pre-split bf16 hi/lo ----
__global__ void prep_weights_kernel(const float* __restrict__ pre_W2,
                                    const float* __restrict__ msg_W1,
                                    const float* __restrict__ msg_W2,
                                    const float* __restrict__ post_W1,
                                    const float* __restrict__ post_W2)
{
    int idx = blockIdx.x * blockDim.x + threadIdx.x;
    if (idx >= NMAT * MAT_ENTRIES) return;
    int t  = idx & 3;
    int c  = (idx >> 2) & 127;
    int kc = (idx >> 9) & 7;
    int m  = idx >> 12;

    const float* W;
    switch (m) {
        case 0: W = pre_W2; break;
        case 1: W = msg_W1; break;
        case 2: W = msg_W1 + H * H; break;
        case 3: W = msg_W2; break;
        case 4: W = post_W1; break;
        case 5: W = post_W1 + H * H; break;
        default: W = post_W2; break;
    }
    int k0 = kc * 16 + 2 * t;
    float w0 = W[(k0    ) * H + c];
    float w1 = W[(k0 + 1) * H + c];
    float w8 = W[(k0 + 8) * H + c];
    float w9 = W[(k0 + 9) * H + c];

    uint32_t h01 = bpack(w0, w1);
    uint32_t l01 = bpack(w0 - bf_lo(h01), w1 - bf_hi(h01));
    uint32_t h89 = bpack(w8, w9);
    uint32_t l89 = bpack(w8 - bf_lo(h89), w9 - bf_hi(h89));

    g_Wpk[idx] = make_uint4(h01, h89, l01, l89);
}

__device__ __forceinline__ void mma_bf16(float* c, const uint32_t* a, const uint32_t* b)
{
    asm volatile(
        "mma.sync.aligned.m16n8k16.row.col.f32.bf16.bf16.f32 "
        "{%0,%1,%2,%3}, {%4,%5,%6,%7}, {%8,%9}, {%0,%1,%2,%3};"
        : "+f"(c[0]), "+f"(c[1]), "+f"(c[2]), "+f"(c[3])
        : "r"(a[0]), "r"(a[1]), "r"(a[2]), "r"(a[3]), "r"(b[0]), "r"(b[1]));
}

// acc += X[32x128] @ W[128x128]; X fp32 in smem (stride AP), W packed bf16 hi/lo in g_Wpk.
// 4 warps: warp w covers output cols w*32..w*32+31 (4 n-tiles m16n8k16), rows 0..31 (2 m-tiles).
// 3xBF16 compensated (hh + lh + hl).
__device__ __forceinline__ void gemm_acc(const float* __restrict__ X,
                                         int mat, float acc[2][4][4])
{
    const uint4* __restrict__ Wp = g_Wpk + mat * MAT_ENTRIES;
    const int lane = threadIdx.x & 31;
    const int warp = threadIdx.x >> 5;
    const int n0 = warp * 32;
    const int g = lane >> 2, tig = lane & 3;

#pragma unroll
    for (int kc = 0; kc < 8; ++kc) {
        const int kk = kc * 16;
        // B-frags: one LDG.128 per n-tile (pre-split, fragment-ordered, coalesced)
        uint4 bfr[4];
#pragma unroll
        for (int nt = 0; nt < 4; ++nt)
            bfr[nt] = __ldg(&Wp[((kc << 7) + n0 + nt * 8 + g) * 4 + tig]);

        // A-frags: fp32 from smem, split to bf16 hi/lo pairs in registers
        uint32_t ah[2][4], al[2][4];
#pragma unroll
        for (int mt = 0; mt < 2; ++mt) {
            int r = mt * 16 + g;
            float2 a01 = *(const float2*)&X[ r      * AP + kk + 2 * tig];
            float2 c01 = *(const float2*)&X[(r + 8) * AP + kk + 2 * tig];
            float2 a89 = *(const float2*)&X[ r      * AP + kk + 2 * tig + 8];
            float2 c89 = *(const float2*)&X[(r + 8) * AP + kk + 2 * tig + 8];
            bsplit2(a01, ah[mt][0], al[mt][0]);
            bsplit2(c01, ah[mt][1], al[mt][1]);
            bsplit2(a89, ah[mt][2], al[mt][2]);
            bsplit2(c89, ah[mt][3], al[mt][3]);
        }
#pragma unroll
        for (int mt = 0; mt < 2; ++mt)
#pragma unroll
            for (int nt = 0; nt < 4; ++nt) {
                uint32_t bh[2] = {bfr[nt].x, bfr[nt].y};
                uint32_t bl[2] = {bfr[nt].z, bfr[nt].w};
                mma_bf16(acc[mt][nt], ah[mt], bh);
                mma_bf16(acc[mt][nt], al[mt], bh);
                mma_bf16(acc[mt][nt], ah[mt], bl);
            }
    }
}

__device__ __forceinline__ void gemm_epi(float acc[2][4][4], float* __restrict__ C,
                                         const float* __restrict__ gbias, float biasScale,
                                         bool doRelu)
{
    const int lane = threadIdx.x & 31;
    const int warp = threadIdx.x >> 5;
    const int n0 = warp * 32;
    const int g = lane >> 2, tig = lane & 3;
#pragma unroll
    for (int mt = 0; mt < 2; ++mt) {
#pragma unroll
        for (int nt = 0; nt < 4; ++nt) {
            int r = mt * 16 + g;
            int c = n0 + nt * 8 + 2 * tig;
#pragma unroll
            for (int h = 0; h < 2; ++h) {
                int rr = r + h * 8;
#pragma unroll
                for (int q = 0; q < 2; ++q) {
                    float v = acc[mt][nt][h * 2 + q];
                    if (gbias) v += biasScale * __ldg(&gbias[c + q]);
                    if (doRelu) v = fmaxf(v, 0.f);
                    C[rr * AP + c + q] = v;
                }
            }
        }
    }
}

#define ACC_ZERO(acc) do {                                             \
    _Pragma("unroll")                                                  \
    for (int _m = 0; _m < 2; ++_m)                                     \
        _Pragma("unroll")                                              \
        for (int _n = 0; _n < 4; ++_n)                                 \
            _Pragma("unroll")                                          \
            for (int _i = 0; _i < 4; ++_i) acc[_m][_n][_i] = 0.f;      \
} while (0)

__global__ __launch_bounds__(NT, 4) void prettyrnn_kernel(
    const int* __restrict__ anchors, const int* __restrict__ n_jumps,
    const float* __restrict__ positions, const int* __restrict__ colors,
    const int* __restrict__ markers,
    const float* __restrict__ pre_W1, const float* __restrict__ pre_b1,
    const float* __restrict__ pre_b2,
    const float* __restrict__ msg_W1, const float* __restrict__ msg_b1,
    const float* __restrict__ msg_b2,
    const float* __restrict__ post_b1, const float* __restrict__ post_b2,
    const float* __restrict__ out_W1, const float* __restrict__ out_b1,
    const float* __restrict__ out_W2, const float* __restrict__ out_b2,
    float* __restrict__ out)
{
    extern __shared__ float sm[];
    float* sX0 = sm + OFF_X0;
    float* sA  = sm + OFF_A;
    float* sB  = sm + OFF_B;
    float* sG  = sm + OFF_G;
    float* sPos = sm + OFF_POS;
    float* sD  = sm + OFF_D;
    int* sCol = (int*)(sm + OFF_INT);
    int* sMrk = sCol + NODES;
    int* sAnc = sMrk + NODES;
    int* sJmp = sAnc + GPC;

    const int tid = threadIdx.x;
    const int nodeBase = blockIdx.x * NODES;
    const int graphBase = blockIdx.x * GPC;
    const int tx = tid & 15;
    const int ty = tid >> 4;
    const int r0 = ty * 4;
    const int c0 = tx * 8;

    // ---- phase 0: per-node / per-graph inputs ----
    if (tid < NODES) {
        sCol[tid] = colors[nodeBase + tid];
        sMrk[tid] = markers[nodeBase + tid];
        sPos[2 * tid]     = positions[2 * (nodeBase + tid)];
        sPos[2 * tid + 1] = positions[2 * (nodeBase + tid) + 1];
    }
    if (tid >= NODES && tid < NODES + GPC) {
        int g = tid - NODES;
        sAnc[g] = anchors[graphBase + g];
        sJmp[g] = n_jumps[graphBase + g];
    }
    __syncthreads();

    // ---- distances ----
    for (int idx = tid; idx < NODES * 8; idx += NT) {
        int n = idx >> 3, jj = idx & 7;
        int j = (n & ~7) + jj;
        float dx = sPos[2 * n]     - sPos[2 * j];
        float dy = sPos[2 * n + 1] - sPos[2 * j + 1];
        sD[idx] = sqrtf(dx * dx + dy * dy);
    }

    // ---- pre layer 1 (one-hot gather from gmem rows) -> sA (fp32, relu) ----
    {
#pragma unroll
        for (int i = 0; i < 4; ++i) {
            int n = r0 + i;
            int g = n >> 3;
            float px = sPos[2 * n], py = sPos[2 * n + 1];
            const float* rw0 = pre_W1;
            const float* rw1 = pre_W1 + H;
            const float* rc = pre_W1 + (2 + sCol[n]) * H;
            const float* rm = pre_W1 + (10 + (sMrk[n] - 8)) * H;
            const float* ra = pre_W1 + (18 + sAnc[g]) * H;
            const float* rj = pre_W1 + (34 + sJmp[g]) * H;
#pragma unroll
            for (int c = 0; c < 8; ++c) {
                int k = c0 + c;
                float v = __ldg(&rc[k]) + __ldg(&rm[k]) + __ldg(&ra[k])
                        + __ldg(&rj[k]) + __ldg(&pre_b1[k]);
                v = fmaf(px, __ldg(&rw0[k]), fmaf(py, __ldg(&rw1[k]), v));
                sA[n * AP + k] = fmaxf(v, 0.f);
            }
        }
    }
    __syncthreads();

    // ---- pre layer 2 (linear): x0 = h1 @ pre_W2 + b2 -> sX0 ----
    {
        float acc[2][4][4]; ACC_ZERO(acc);
        gemm_acc(sA, 0, acc);
        gemm_epi(acc, sX0, pre_b2, 1.f, false);
    }
    __syncthreads();

    // ---- A = x0 @ msg_W1[0:128] -> sA ; B = x0 @ msg_W1[128:256] -> sB ----
    {
        float acc[2][4][4]; ACC_ZERO(acc);
        gemm_acc(sX0, 1, acc);
        gemm_epi(acc, sA, nullptr, 0.f, false);
    }
    {
        float acc[2][4][4]; ACC_ZERO(acc);
        gemm_acc(sX0, 2, acc);
        gemm_epi(acc, sB, nullptr, 0.f, false);
    }
    __syncthreads();

    // ---- edge aggregation: s[n] = sum_{j!=n} relu(A[n]+B[j]+d*w1d+b1) -> sA ----
    {
        const float* w1d = msg_W1 + 2 * H * H;
        float wv[8], bv[8];
#pragma unroll
        for (int c = 0; c < 8; ++c) {
            wv[c] = __ldg(&w1d[c0 + c]);
            bv[c] = __ldg(&msg_b1[c0 + c]);
        }
#pragma unroll
        for (int i = 0; i < 4; ++i) {
            int n = r0 + i, nb = n & ~7, nloc = n & 7;
            float a[8];
            {
                float4 a0 = *(const float4*)&sA[n * AP + c0];
                float4 a1 = *(const float4*)&sA[n * AP + c0 + 4];
                a[0]=a0.x; a[1]=a0.y; a[2]=a0.z; a[3]=a0.w; a[4]=a1.x; a[5]=a1.y; a[6]=a1.z; a[7]=a1.w;
            }
            float s[8] = {0,0,0,0,0,0,0,0};
#pragma unroll
            for (int jj = 0; jj < 8; ++jj) {
                if (jj == nloc) continue;
                float d = sD[n * 8 + jj];
                const float* bp = sB + (nb + jj) * AP + c0;
                float4 b0 = *(const float4*)bp;
                float4 b1 = *(const float4*)(bp + 4);
                float bb[8] = {b0.x, b0.y, b0.z, b0.w, b1.x, b1.y, b1.z, b1.w};
#pragma unroll
                for (int c = 0; c < 8; ++c) {
                    float t = a[c] + bb[c] + fmaf(d, wv[c], bv[c]);
                    s[c] += fmaxf(t, 0.f);
                }
            }
            *(float4*)&sA[n * AP + c0]     = make_float4(s[0], s[1], s[2], s[3]);
            *(float4*)&sA[n * AP + c0 + 4] = make_float4(s[4], s[5], s[6], s[7]);
        }
    }
    __syncthreads();

    // ---- upd = s @ msg_W2 + 7*msg_b2 -> sB ----
    {
        float acc[2][4][4]; ACC_ZERO(acc);
        gemm_acc(sA, 3, acc);
        gemm_epi(acc, sB, msg_b2, 7.f, false);
    }
    __syncthreads();

    // ---- post layer 1 (fused 2K): h = relu(upd@P1a + x0@P1b + b1) -> sA ----
    {
        float acc[2][4][4]; ACC_ZERO(acc);
        gemm_acc(sB,  4, acc);
        gemm_acc(sX0, 5, acc);
        gemm_epi(acc, sA, post_b1, 1.f, true);
    }
    __syncthreads();

    // ---- post layer 2: x = h @ post_W2 + b2 -> sB ----
    {
        float acc[2][4][4]; ACC_ZERO(acc);
        gemm_acc(sA, 6, acc);
        gemm_epi(acc, sB, post_b2, 1.f, false);
    }
    __syncthreads();

    // ---- graph sum -> sG ----
    for (int idx = tid; idx < GPC * H; idx += NT) {
        int g = idx >> 7, k = idx & (H - 1);
        float s = 0.f;
#pragma unroll
        for (int i = 0; i < 8; ++i) s += sB[(g * 8 + i) * AP + k];
        sG[g * AP + k] = s;
    }
    __syncthreads();

    // ---- out layer 1 (SIMT): col k=tid fixed per thread ----
    {
        float s0 = __ldg(&out_b1[tid]);
        float s1 = s0, s2 = s0, s3 = s0;
#pragma unroll 4
        for (int kk = 0; kk < H; ++kk) {
            float w = __ldg(&out_W1[kk * H + tid]);
            s0 = fmaf(sG[0 * AP + kk], w, s0);
            s1 = fmaf(sG[1 * AP + kk], w, s1);
            s2 = fmaf(sG[2 * AP + kk], w, s2);
            s3 = fmaf(sG[3 * AP + kk], w, s3);
        }
        sB[0 * AP + tid] = fmaxf(s0, 0.f);
        sB[1 * AP + tid] = fmaxf(s1, 0.f);
        sB[2 * AP + tid] = fmaxf(s2, 0.f);
        sB[3 * AP + tid] = fmaxf(s3, 0.f);
    }
    __syncthreads();

    // ---- out layer 2 (SIMT): logits -> gmem ----
    if (tid < GPC * 16) {
        int g = tid >> 4, o = tid & 15;
        float s = __ldg(&out_b2[o]);
#pragma unroll 8
        for (int k = 0; k < H; ++k)
            s = fmaf(sB[g * AP + k], __ldg(&out_W2[k * 16 + o]), s);
        out[(graphBase + g) * 16 + o] = s;
    }
}

extern "C" void kernel_launch(void* const* d_in, const int* in_sizes, int n_in,
                              void* d_out, int out_size)
{
    const int*   anchors   = (const int*)d_in[0];
    const int*   n_jumps   = (const int*)d_in[1];
    const float* positions = (const float*)d_in[2];
    const int*   colors    = (const int*)d_in[3];
    const int*   markers   = (const int*)d_in[4];
    const float* pre_W1  = (const float*)d_in[5];
    const float* pre_b1  = (const float*)d_in[6];
    const float* pre_W2  = (const float*)d_in[7];
    const float* pre_b2  = (const float*)d_in[8];
    const float* msg_W1  = (const float*)d_in[9];
    const float* msg_b1  = (const float*)d_in[10];
    const float* msg_W2  = (const float*)d_in[11];
    const float* msg_b2  = (const float*)d_in[12];
    const float* post_W1 = (const float*)d_in[13];
    const float* post_b1 = (const float*)d_in[14];
    const float* post_W2 = (const float*)d_in[15];
    const float* post_b2 = (const float*)d_in[16];
    const float* out_W1  = (const float*)d_in[17];
    const float* out_b1  = (const float*)d_in[18];
    const float* out_W2  = (const float*)d_in[19];
    const float* out_b2  = (const float*)d_in[20];

    // 1) pack + pre-split weights (same every call: deterministic, graph-capturable)
    int prepThreads = NMAT * MAT_ENTRIES;
    prep_weights_kernel<<<(prepThreads + 255) / 256, 256>>>(
        pre_W2, msg_W1, msg_W2, post_W1, post_W2);

    // 2) main fused kernel
    int bs = in_sizes[0];
    int blocks = bs / GPC;
    size_t smemBytes = SMEM_FLOATS * sizeof(float);
    cudaFuncSetAttribute(prettyrnn_kernel,
                         cudaFuncAttributeMaxDynamicSharedMemorySize, (int)smemBytes);
    prettyrnn_kernel<<<blocks, NT, smemBytes>>>(
        anchors, n_jumps, positions, colors, markers,
        pre_W1, pre_b1, pre_b2,
        msg_W1, msg_b1, msg_b2,
        post_b1, post_b2,
        out_W1, out_b1, out_W2, out_b2,
        (float*)d_out);
}

// round 9
// speedup vs baseline: 2.8531x; 1.1302x over previous
#include <cuda_runtime.h>
#include <cuda_bf16.h>
#include <cstdint>
#include <math.h>

#define H 128
#define AP 136           // activation stride (floats); 136 % 32 == 8 -> conflict-free LDS.64
#define NODES 32         // nodes per CTA
#define GPC 4            // graphs per CTA
#define NT 128

// shared layout (float offsets) -- activations only
#define OFF_X0 0
#define OFF_A  (OFF_X0 + NODES*AP)     // 4352
#define OFF_B  (OFF_A  + NODES*AP)     // 8704
#define OFF_G  (OFF_B  + NODES*AP)     // 13056
#define OFF_POS (OFF_G + GPC*AP)       // 13600
#define OFF_D  (OFF_POS + NODES*2)     // 13664
#define OFF_INT (OFF_D + NODES*8)      // 13920
#define SMEM_FLOATS (OFF_INT + 80)     // 14000 floats = 56000 B -> 4 CTAs/SM

// packed weights: 7 matrices x [kc(8)][c(128)][t(4)] entries of uint4 {bh01, bh89, bl01, bl89}
#define NMAT 7
#define MAT_ENTRIES (8 * 128 * 4)      // 4096 uint4 per matrix
__device__ uint4 g_Wpk[NMAT * MAT_ENTRIES];   // 448 KB

// ---- bf16 helpers ----
__device__ __forceinline__ uint32_t bpack(float lo, float hi) {   // lo -> bits[0:16), hi -> bits[16:32)
    uint32_t r;
    asm("cvt.rn.bf16x2.f32 %0, %1, %2;" : "=r"(r) : "f"(hi), "f"(lo));
    return r;
}
__device__ __forceinline__ float bf_lo(uint32_t p) { return __uint_as_float(p << 16); }
__device__ __forceinline__ float bf_hi(uint32_t p) { return __uint_as_float(p & 0xffff0000u); }

// split a float2 (consecutive k) into packed bf16 hi-pair and lo-pair
__device__ __forceinline__ void bsplit2(float2 v, uint32_t& h, uint32_t& l) {
    h = bpack(v.x, v.y);
    l = bpack(v.x - bf_lo(h), v.y - bf_hi(h));
}

// ---- prep kernel: pack weight matrices into mma-B-fragment order, pre-split bf16 hi/lo ----
__global__ void prep_weights_kernel(const float* __restrict__ pre_W2,
                                    const float* __restrict__ msg_W1,
                                    const float* __restrict__ msg_W2,
                                    const float* __restrict__ post_W1,
                                    const float* __restrict__ post_W2)
{
    int idx = blockIdx.x * blockDim.x + threadIdx.x;
    if (idx >= NMAT * MAT_ENTRIES) return;
    int t  = idx & 3;
    int c  = (idx >> 2) & 127;
    int kc = (idx >> 9) & 7;
    int m  = idx >> 12;

    const float* W;
    switch (m) {
        case 0: W = pre_W2; break;
        case 1: W = msg_W1; break;
        case 2: W = msg_W1 + H * H; break;
        case 3: W = msg_W2; break;
        case 4: W = post_W1; break;
        case 5: W = post_W1 + H * H; break;
        default: W = post_W2; break;
    }
    int k0 = kc * 16 + 2 * t;
    float w0 = W[(k0    ) * H + c];
    float w1 = W[(k0 + 1) * H + c];
    float w8 = W[(k0 + 8) * H + c];
    float w9 = W[(k0 + 9) * H + c];

    uint32_t h01 = bpack(w0, w1);
    uint32_t l01 = bpack(w0 - bf_lo(h01), w1 - bf_hi(h01));
    uint32_t h89 = bpack(w8, w9);
    uint32_t l89 = bpack(w8 - bf_lo(h89), w9 - bf_hi(h89));

    g_Wpk[idx] = make_uint4(h01, h89, l01, l89);
}

__device__ __forceinline__ void mma_bf16(float* c, const uint32_t* a, const uint32_t* b)
{
    asm volatile(
        "mma.sync.aligned.m16n8k16.row.col.f32.bf16.bf16.f32 "
        "{%0,%1,%2,%3}, {%4,%5,%6,%7}, {%8,%9}, {%0,%1,%2,%3};"
        : "+f"(c[0]), "+f"(c[1]), "+f"(c[2]), "+f"(c[3])
        : "r"(a[0]), "r"(a[1]), "r"(a[2]), "r"(a[3]), "r"(b[0]), "r"(b[1]));
}

// acc += X[32x128] @ W[128x128]; X fp32 in smem (stride AP), W packed bf16 hi/lo in g_Wpk.
// 4 warps: warp w covers output cols w*32..w*32+31 (4 n-tiles m16n8k16), rows 0..31 (2 m-tiles).
// 3xBF16 compensated (hh + lh + hl).
__device__ __forceinline__ void gemm_acc(const float* __restrict__ X,
                                         int mat, float acc[2][4][4])
{
    const uint4* __restrict__ Wp = g_Wpk + mat * MAT_ENTRIES;
    const int lane = threadIdx.x & 31;
    const int warp = threadIdx.x >> 5;
    const int n0 = warp * 32;
    const int g = lane >> 2, tig = lane & 3;

#pragma unroll
    for (int kc = 0; kc < 8; ++kc) {
        const int kk = kc * 16;
        // B-frags: one LDG.128 per n-tile (pre-split, fragment-ordered, coalesced)
        uint4 bfr[4];
#pragma unroll
        for (int nt = 0; nt < 4; ++nt)
            bfr[nt] = __ldg(&Wp[((kc << 7) + n0 + nt * 8 + g) * 4 + tig]);

        // A-frags: fp32 from smem (conflict-free at AP%32==8), split to bf16 hi/lo in regs
        uint32_t ah[2][4], al[2][4];
#pragma unroll
        for (int mt = 0; mt < 2; ++mt) {
            int r = mt * 16 + g;
            float2 a01 = *(const float2*)&X[ r      * AP + kk + 2 * tig];
            float2 c01 = *(const float2*)&X[(r + 8) * AP + kk + 2 * tig];
            float2 a89 = *(const float2*)&X[ r      * AP + kk + 2 * tig + 8];
            float2 c89 = *(const float2*)&X[(r + 8) * AP + kk + 2 * tig + 8];
            bsplit2(a01, ah[mt][0], al[mt][0]);
            bsplit2(c01, ah[mt][1], al[mt][1]);
            bsplit2(a89, ah[mt][2], al[mt][2]);
            bsplit2(c89, ah[mt][3], al[mt][3]);
        }
#pragma unroll
        for (int mt = 0; mt < 2; ++mt)
#pragma unroll
            for (int nt = 0; nt < 4; ++nt) {
                uint32_t bh[2] = {bfr[nt].x, bfr[nt].y};
                uint32_t bl[2] = {bfr[nt].z, bfr[nt].w};
                mma_bf16(acc[mt][nt], ah[mt], bh);
                mma_bf16(acc[mt][nt], al[mt], bh);
                mma_bf16(acc[mt][nt], ah[mt], bl);
            }
    }
}

// vectorized epilogue: float2 stores, float2 bias loads
__device__ __forceinline__ void gemm_epi(float acc[2][4][4], float* __restrict__ C,
                                         const float* __restrict__ gbias, float biasScale,
                                         bool doRelu)
{
    const int lane = threadIdx.x & 31;
    const int warp = threadIdx.x >> 5;
    const int n0 = warp * 32;
    const int g = lane >> 2, tig = lane & 3;
#pragma unroll
    for (int nt = 0; nt < 4; ++nt) {
        int c = n0 + nt * 8 + 2 * tig;
        float2 bz = make_float2(0.f, 0.f);
        if (gbias) {
            float2 b = *(const float2*)&gbias[c];   // L1/L2-hot, read-only
            bz.x = biasScale * b.x; bz.y = biasScale * b.y;
        }
#pragma unroll
        for (int mt = 0; mt < 2; ++mt) {
            int r = mt * 16 + g;
#pragma unroll
            for (int h = 0; h < 2; ++h) {
                int rr = r + h * 8;
                float vx = acc[mt][nt][h * 2 + 0] + bz.x;
                float vy = acc[mt][nt][h * 2 + 1] + bz.y;
                if (doRelu) { vx = fmaxf(vx, 0.f); vy = fmaxf(vy, 0.f); }
                *(float2*)&C[rr * AP + c] = make_float2(vx, vy);
            }
        }
    }
}

#define ACC_ZERO(acc) do {                                             \
    _Pragma("unroll")                                                  \
    for (int _m = 0; _m < 2; ++_m)                                     \
        _Pragma("unroll")                                              \
        for (int _n = 0; _n < 4; ++_n)                                 \
            _Pragma("unroll")                                          \
            for (int _i = 0; _i < 4; ++_i) acc[_m][_n][_i] = 0.f;      \
} while (0)

__global__ __launch_bounds__(NT, 4) void prettyrnn_kernel(
    const int* __restrict__ anchors, const int* __restrict__ n_jumps,
    const float* __restrict__ positions, const int* __restrict__ colors,
    const int* __restrict__ markers,
    const float* __restrict__ pre_W1, const float* __restrict__ pre_b1,
    const float* __restrict__ pre_b2,
    const float* __restrict__ msg_W1, const float* __restrict__ msg_b1,
    const float* __restrict__ msg_b2,
    const float* __restrict__ post_b1, const float* __restrict__ post_b2,
    const float* __restrict__ out_W1, const float* __restrict__ out_b1,
    const float* __restrict__ out_W2, const float* __restrict__ out_b2,
    float* __restrict__ out)
{
    extern __shared__ float sm[];
    float* sX0 = sm + OFF_X0;
    float* sA  = sm + OFF_A;
    float* sB  = sm + OFF_B;
    float* sG  = sm + OFF_G;
    float* sPos = sm + OFF_POS;
    float* sD  = sm + OFF_D;
    int* sCol = (int*)(sm + OFF_INT);
    int* sMrk = sCol + NODES;
    int* sAnc = sMrk + NODES;
    int* sJmp = sAnc + GPC;

    const int tid = threadIdx.x;
    const int nodeBase = blockIdx.x * NODES;
    const int graphBase = blockIdx.x * GPC;
    const int tx = tid & 15;
    const int ty = tid >> 4;
    const int r0 = ty * 4;
    const int c0 = tx * 8;

    // ---- phase 0: per-node / per-graph inputs ----
    if (tid < NODES) {
        sCol[tid] = colors[nodeBase + tid];
        sMrk[tid] = markers[nodeBase + tid];
        sPos[2 * tid]     = positions[2 * (nodeBase + tid)];
        sPos[2 * tid + 1] = positions[2 * (nodeBase + tid) + 1];
    }
    if (tid >= NODES && tid < NODES + GPC) {
        int g = tid - NODES;
        sAnc[g] = anchors[graphBase + g];
        sJmp[g] = n_jumps[graphBase + g];
    }
    __syncthreads();

    // ---- distances ----
    for (int idx = tid; idx < NODES * 8; idx += NT) {
        int n = idx >> 3, jj = idx & 7;
        int j = (n & ~7) + jj;
        float dx = sPos[2 * n]     - sPos[2 * j];
        float dy = sPos[2 * n + 1] - sPos[2 * j + 1];
        sD[idx] = sqrtf(dx * dx + dy * dy);
    }

    // ---- pre layer 1 (one-hot gather from gmem rows) -> sA (fp32, relu) ----
    {
#pragma unroll
        for (int i = 0; i < 4; ++i) {
            int n = r0 + i;
            int g = n >> 3;
            float px = sPos[2 * n], py = sPos[2 * n + 1];
            const float* rw0 = pre_W1;
            const float* rw1 = pre_W1 + H;
            const float* rc = pre_W1 + (2 + sCol[n]) * H;
            const float* rm = pre_W1 + (10 + (sMrk[n] - 8)) * H;
            const float* ra = pre_W1 + (18 + sAnc[g]) * H;
            const float* rj = pre_W1 + (34 + sJmp[g]) * H;
#pragma unroll
            for (int c = 0; c < 8; ++c) {
                int k = c0 + c;
                float v = __ldg(&rc[k]) + __ldg(&rm[k]) + __ldg(&ra[k])
                        + __ldg(&rj[k]) + __ldg(&pre_b1[k]);
                v = fmaf(px, __ldg(&rw0[k]), fmaf(py, __ldg(&rw1[k]), v));
                sA[n * AP + k] = fmaxf(v, 0.f);
            }
        }
    }
    __syncthreads();

    // ---- pre layer 2 (linear): x0 = h1 @ pre_W2 + b2 -> sX0 ----
    {
        float acc[2][4][4]; ACC_ZERO(acc);
        gemm_acc(sA, 0, acc);
        gemm_epi(acc, sX0, pre_b2, 1.f, false);
    }
    __syncthreads();

    // ---- A = x0 @ msg_W1[0:128] -> sA ; B = x0 @ msg_W1[128:256] -> sB ----
    {
        float acc[2][4][4]; ACC_ZERO(acc);
        gemm_acc(sX0, 1, acc);
        gemm_epi(acc, sA, nullptr, 0.f, false);
    }
    {
        float acc[2][4][4]; ACC_ZERO(acc);
        gemm_acc(sX0, 2, acc);
        gemm_epi(acc, sB, nullptr, 0.f, false);
    }
    __syncthreads();

    // ---- edge aggregation: s[n] = sum_{j!=n} relu(A[n]+B[j]+d*w1d+b1) -> sA ----
    {
        const float* w1d = msg_W1 + 2 * H * H;
        float wv[8], bv[8];
#pragma unroll
        for (int c = 0; c < 8; ++c) {
            wv[c] = __ldg(&w1d[c0 + c]);
            bv[c] = __ldg(&msg_b1[c0 + c]);
        }
#pragma unroll
        for (int i = 0; i < 4; ++i) {
            int n = r0 + i, nb = n & ~7, nloc = n & 7;
            float a[8];
            {
                float4 a0 = *(const float4*)&sA[n * AP + c0];
                float4 a1 = *(const float4*)&sA[n * AP + c0 + 4];
                a[0]=a0.x; a[1]=a0.y; a[2]=a0.z; a[3]=a0.w; a[4]=a1.x; a[5]=a1.y; a[6]=a1.z; a[7]=a1.w;
            }
            float s[8] = {0,0,0,0,0,0,0,0};
#pragma unroll
            for (int jj = 0; jj < 8; ++jj) {
                if (jj == nloc) continue;
                float d = sD[n * 8 + jj];
                const float* bp = sB + (nb + jj) * AP + c0;
                float4 b0 = *(const float4*)bp;
                float4 b1 = *(const float4*)(bp + 4);
                float bb[8] = {b0.x, b0.y, b0.z, b0.w, b1.x, b1.y, b1.z, b1.w};
#pragma unroll
                for (int c = 0; c < 8; ++c) {
                    float t = a[c] + bb[c] + fmaf(d, wv[c], bv[c]);
                    s[c] += fmaxf(t, 0.f);
                }
            }
            *(float4*)&sA[n * AP + c0]     = make_float4(s[0], s[1], s[2], s[3]);
            *(float4*)&sA[n * AP + c0 + 4] = make_float4(s[4], s[5], s[6], s[7]);
        }
    }
    __syncthreads();

    // ---- upd = s @ msg_W2 + 7*msg_b2 -> sB ----
    {
        float acc[2][4][4]; ACC_ZERO(acc);
        gemm_acc(sA, 3, acc);
        gemm_epi(acc, sB, msg_b2, 7.f, false);
    }
    __syncthreads();

    // ---- post layer 1 (fused 2K): h = relu(upd@P1a + x0@P1b + b1) -> sA ----
    {
        float acc[2][4][4]; ACC_ZERO(acc);
        gemm_acc(sB,  4, acc);
        gemm_acc(sX0, 5, acc);
        gemm_epi(acc, sA, post_b1, 1.f, true);
    }
    __syncthreads();

    // ---- post layer 2: x = h @ post_W2 + b2 -> sB ----
    {
        float acc[2][4][4]; ACC_ZERO(acc);
        gemm_acc(sA, 6, acc);
        gemm_epi(acc, sB, post_b2, 1.f, false);
    }
    __syncthreads();

    // ---- graph sum -> sG ----
    for (int idx = tid; idx < GPC * H; idx += NT) {
        int g = idx >> 7, k = idx & (H - 1);
        float s = 0.f;
#pragma unroll
        for (int i = 0; i < 8; ++i) s += sB[(g * 8 + i) * AP + k];
        sG[g * AP + k] = s;
    }
    __syncthreads();

    // ---- out layer 1 (SIMT): col k=tid fixed per thread ----
    {
        float s0 = __ldg(&out_b1[tid]);
        float s1 = s0, s2 = s0, s3 = s0;
#pragma unroll 4
        for (int kk = 0; kk < H; ++kk) {
            float w = __ldg(&out_W1[kk * H + tid]);
            s0 = fmaf(sG[0 * AP + kk], w, s0);
            s1 = fmaf(sG[1 * AP + kk], w, s1);
            s2 = fmaf(sG[2 * AP + kk], w, s2);
            s3 = fmaf(sG[3 * AP + kk], w, s3);
        }
        sB[0 * AP + tid] = fmaxf(s0, 0.f);
        sB[1 * AP + tid] = fmaxf(s1, 0.f);
        sB[2 * AP + tid] = fmaxf(s2, 0.f);
        sB[3 * AP + tid] = fmaxf(s3, 0.f);
    }
    __syncthreads();

    // ---- out layer 2 (SIMT): logits -> gmem ----
    if (tid < GPC * 16) {
        int g = tid >> 4, o = tid & 15;
        float s = __ldg(&out_b2[o]);
#pragma unroll 8
        for (int k = 0; k < H; ++k)
            s = fmaf(sB[g * AP + k], __ldg(&out_W2[k * 16 + o]), s);
        out[(graphBase + g) * 16 + o] = s;
    }
}

extern "C" void kernel_launch(void* const* d_in, const int* in_sizes, int n_in,
                              void* d_out, int out_size)
{
    const int*   anchors   = (const int*)d_in[0];
    const int*   n_jumps   = (const int*)d_in[1];
    const float* positions = (const float*)d_in[2];
    const int*   colors    = (const int*)d_in[3];
    const int*   markers   = (const int*)d_in[4];
    const float* pre_W1  = (const float*)d_in[5];
    const float* pre_b1  = (const float*)d_in[6];
    const float* pre_W2  = (const float*)d_in[7];
    const float* pre_b2  = (const float*)d_in[8];
    const float* msg_W1  = (const float*)d_in[9];
    const float* msg_b1  = (const float*)d_in[10];
    const float* msg_W2  = (const float*)d_in[11];
    const float* msg_b2  = (const float*)d_in[12];
    const float* post_W1 = (const float*)d_in[13];
    const float* post_b1 = (const float*)d_in[14];
    const float* post_W2 = (const float*)d_in[15];
    const float* post_b2 = (const float*)d_in[16];
    const float* out_W1  = (const float*)d_in[17];
    const float* out_b1  = (const float*)d_in[18];
    const float* out_W2  = (const float*)d_in[19];
    const float* out_b2  = (const float*)d_in[20];

    // 1) pack + pre-split weights (same every call: deterministic, graph-capturable)
    int prepThreads = NMAT * MAT_ENTRIES;
    prep_weights_kernel<<<(prepThreads + 255) / 256, 256>>>(
        pre_W2, msg_W1, msg_W2, post_W1, post_W2);

    // 2) main fused kernel
    int bs = in_sizes[0];
    int blocks = bs / GPC;
    size_t smemBytes = SMEM_FLOATS * sizeof(float);
    cudaFuncSetAttribute(prettyrnn_kernel,
                         cudaFuncAttributeMaxDynamicSharedMemorySize, (int)smemBytes);
    prettyrnn_kernel<<<blocks, NT, smemBytes>>>(
        anchors, n_jumps, positions, colors, markers,
        pre_W1, pre_b1, pre_b2,
        msg_W1, msg_b1, msg_b2,
        post_b1, post_b2,
        out_W1, out_b1, out_W2, out_b2,
        (float*)d_out);
}

// round 10
// speedup vs baseline: 3.0757x; 1.0780x over previous
#include <cuda_runtime.h>
#include <cuda_bf16.h>
#include <cstdint>
#include <math.h>

#define H 128
#define AP 136           // activation stride (floats); 136 % 32 == 8 -> conflict-free LDS.64
#define NODES 32         // nodes per CTA
#define GPC 4            // graphs per CTA
#define NT 128

// shared layout (float offsets) -- activations only
#define OFF_X0 0
#define OFF_A  (OFF_X0 + NODES*AP)     // 4352
#define OFF_B  (OFF_A  + NODES*AP)     // 8704
#define OFF_G  (OFF_B  + NODES*AP)     // 13056
#define OFF_POS (OFF_G + GPC*AP)       // 13600
#define OFF_D  (OFF_POS + NODES*2)     // 13664
#define OFF_INT (OFF_D + NODES*8)      // 13920
#define SMEM_FLOATS (OFF_INT + 80)     // 14000 floats = 56000 B -> 4 CTAs/SM

// packed weights: 7 matrices x [kc(8)][c(128)][t(4)] entries of uint4 {bh01, bh89, bl01, bl89}
#define NMAT 7
#define MAT_ENTRIES (8 * 128 * 4)      // 4096 uint4 per matrix
__device__ uint4 g_Wpk[NMAT * MAT_ENTRIES];   // 448 KB

// ---- bf16 helpers ----
__device__ __forceinline__ uint32_t bpack(float lo, float hi) {   // lo -> bits[0:16), hi -> bits[16:32)
    uint32_t r;
    asm("cvt.rn.bf16x2.f32 %0, %1, %2;" : "=r"(r) : "f"(hi), "f"(lo));
    return r;
}
__device__ __forceinline__ float bf_lo(uint32_t p) { return __uint_as_float(p << 16); }
__device__ __forceinline__ float bf_hi(uint32_t p) { return __uint_as_float(p & 0xffff0000u); }

// split a float2 (consecutive k) into packed bf16 hi-pair and lo-pair
__device__ __forceinline__ void bsplit2(float2 v, uint32_t& h, uint32_t& l) {
    h = bpack(v.x, v.y);
    l = bpack(v.x - bf_lo(h), v.y - bf_hi(h));
}

// ---- prep kernel: pack weight matrices into mma-B-fragment order, pre-split bf16 hi/lo ----
__global__ void prep_weights_kernel(const float* __restrict__ pre_W2,
                                    const float* __restrict__ msg_W1,
                                    const float* __restrict__ msg_W2,
                                    const float* __restrict__ post_W1,
                                    const float* __restrict__ post_W2)
{
    int idx = blockIdx.x * blockDim.x + threadIdx.x;
    if (idx >= NMAT * MAT_ENTRIES) return;
    int t  = idx & 3;
    int c  = (idx >> 2) & 127;
    int kc = (idx >> 9) & 7;
    int m  = idx >> 12;

    const float* W;
    switch (m) {
        case 0: W = pre_W2; break;
        case 1: W = msg_W1; break;
        case 2: W = msg_W1 + H * H; break;
        case 3: W = msg_W2; break;
        case 4: W = post_W1; break;
        case 5: W = post_W1 + H * H; break;
        default: W = post_W2; break;
    }
    int k0 = kc * 16 + 2 * t;
    float w0 = W[(k0    ) * H + c];
    float w1 = W[(k0 + 1) * H + c];
    float w8 = W[(k0 + 8) * H + c];
    float w9 = W[(k0 + 9) * H + c];

    uint32_t h01 = bpack(w0, w1);
    uint32_t l01 = bpack(w0 - bf_lo(h01), w1 - bf_hi(h01));
    uint32_t h89 = bpack(w8, w9);
    uint32_t l89 = bpack(w8 - bf_lo(h89), w9 - bf_hi(h89));

    g_Wpk[idx] = make_uint4(h01, h89, l01, l89);
}

__device__ __forceinline__ void mma_bf16(float* c, const uint32_t* a, const uint32_t* b)
{
    asm volatile(
        "mma.sync.aligned.m16n8k16.row.col.f32.bf16.bf16.f32 "
        "{%0,%1,%2,%3}, {%4,%5,%6,%7}, {%8,%9}, {%0,%1,%2,%3};"
        : "+f"(c[0]), "+f"(c[1]), "+f"(c[2]), "+f"(c[3])
        : "r"(a[0]), "r"(a[1]), "r"(a[2]), "r"(a[3]), "r"(b[0]), "r"(b[1]));
}

// acc += X[32x128] @ W[128x128]; X fp32 in smem (stride AP), W packed bf16 hi/lo in g_Wpk.
// 4 warps: warp w covers output cols w*32..w*32+31 (4 n-tiles m16n8k16), rows 0..31 (2 m-tiles).
// 3xBF16 compensated (hh + lh + hl).
__device__ __forceinline__ void gemm_acc(const float* __restrict__ X,
                                         int mat, float acc[2][4][4])
{
    const uint4* __restrict__ Wp = g_Wpk + mat * MAT_ENTRIES;
    const int lane = threadIdx.x & 31;
    const int warp = threadIdx.x >> 5;
    const int n0 = warp * 32;
    const int g = lane >> 2, tig = lane & 3;

#pragma unroll
    for (int kc = 0; kc < 8; ++kc) {
        const int kk = kc * 16;
        // B-frags: one LDG.128 per n-tile (pre-split, fragment-ordered, coalesced)
        uint4 bfr[4];
#pragma unroll
        for (int nt = 0; nt < 4; ++nt)
            bfr[nt] = __ldg(&Wp[((kc << 7) + n0 + nt * 8 + g) * 4 + tig]);

        // A-frags: fp32 from smem (conflict-free at AP%32==8), split to bf16 hi/lo in regs
        uint32_t ah[2][4], al[2][4];
#pragma unroll
        for (int mt = 0; mt < 2; ++mt) {
            int r = mt * 16 + g;
            float2 a01 = *(const float2*)&X[ r      * AP + kk + 2 * tig];
            float2 c01 = *(const float2*)&X[(r + 8) * AP + kk + 2 * tig];
            float2 a89 = *(const float2*)&X[ r      * AP + kk + 2 * tig + 8];
            float2 c89 = *(const float2*)&X[(r + 8) * AP + kk + 2 * tig + 8];
            bsplit2(a01, ah[mt][0], al[mt][0]);
            bsplit2(c01, ah[mt][1], al[mt][1]);
            bsplit2(a89, ah[mt][2], al[mt][2]);
            bsplit2(c89, ah[mt][3], al[mt][3]);
        }
#pragma unroll
        for (int mt = 0; mt < 2; ++mt)
#pragma unroll
            for (int nt = 0; nt < 4; ++nt) {
                uint32_t bh[2] = {bfr[nt].x, bfr[nt].y};
                uint32_t bl[2] = {bfr[nt].z, bfr[nt].w};
                mma_bf16(acc[mt][nt], ah[mt], bh);
                mma_bf16(acc[mt][nt], al[mt], bh);
                mma_bf16(acc[mt][nt], ah[mt], bl);
            }
    }
}

// vectorized epilogue: float2 stores, float2 bias loads
__device__ __forceinline__ void gemm_epi(float acc[2][4][4], float* __restrict__ C,
                                         const float* __restrict__ gbias, float biasScale,
                                         bool doRelu)
{
    const int lane = threadIdx.x & 31;
    const int warp = threadIdx.x >> 5;
    const int n0 = warp * 32;
    const int g = lane >> 2, tig = lane & 3;
#pragma unroll
    for (int nt = 0; nt < 4; ++nt) {
        int c = n0 + nt * 8 + 2 * tig;
        float2 bz = make_float2(0.f, 0.f);
        if (gbias) {
            float2 b = *(const float2*)&gbias[c];   // L1/L2-hot, read-only
            bz.x = biasScale * b.x; bz.y = biasScale * b.y;
        }
#pragma unroll
        for (int mt = 0; mt < 2; ++mt) {
            int r = mt * 16 + g;
#pragma unroll
            for (int h = 0; h < 2; ++h) {
                int rr = r + h * 8;
                float vx = acc[mt][nt][h * 2 + 0] + bz.x;
                float vy = acc[mt][nt][h * 2 + 1] + bz.y;
                if (doRelu) { vx = fmaxf(vx, 0.f); vy = fmaxf(vy, 0.f); }
                *(float2*)&C[rr * AP + c] = make_float2(vx, vy);
            }
        }
    }
}

#define ACC_ZERO(acc) do {                                             \
    _Pragma("unroll")                                                  \
    for (int _m = 0; _m < 2; ++_m)                                     \
        _Pragma("unroll")                                              \
        for (int _n = 0; _n < 4; ++_n)                                 \
            _Pragma("unroll")                                          \
            for (int _i = 0; _i < 4; ++_i) acc[_m][_n][_i] = 0.f;      \
} while (0)

__global__ __launch_bounds__(NT, 4) void prettyrnn_kernel(
    const int* __restrict__ anchors, const int* __restrict__ n_jumps,
    const float* __restrict__ positions, const int* __restrict__ colors,
    const int* __restrict__ markers,
    const float* __restrict__ pre_W1, const float* __restrict__ pre_b1,
    const float* __restrict__ pre_b2,
    const float* __restrict__ msg_W1, const float* __restrict__ msg_b1,
    const float* __restrict__ msg_b2,
    const float* __restrict__ post_b1, const float* __restrict__ post_b2,
    const float* __restrict__ out_W1, const float* __restrict__ out_b1,
    const float* __restrict__ out_W2, const float* __restrict__ out_b2,
    float* __restrict__ out)
{
    extern __shared__ float sm[];
    float* sX0 = sm + OFF_X0;
    float* sA  = sm + OFF_A;
    float* sB  = sm + OFF_B;
    float* sG  = sm + OFF_G;
    float* sPos = sm + OFF_POS;
    float* sD  = sm + OFF_D;
    int* sCol = (int*)(sm + OFF_INT);
    int* sMrk = sCol + NODES;
    int* sAnc = sMrk + NODES;
    int* sJmp = sAnc + GPC;

    const int tid = threadIdx.x;
    const int lane = tid & 31;
    const int warp = tid >> 5;
    const int nodeBase = blockIdx.x * NODES;
    const int graphBase = blockIdx.x * GPC;
    const int tx = tid & 15;
    const int ty = tid >> 4;
    const int r0 = ty * 4;
    const int c0 = tx * 8;

    // ---- phase 0: per-node / per-graph inputs ----
    if (tid < NODES) {
        sCol[tid] = colors[nodeBase + tid];
        sMrk[tid] = markers[nodeBase + tid];
        sPos[2 * tid]     = positions[2 * (nodeBase + tid)];
        sPos[2 * tid + 1] = positions[2 * (nodeBase + tid) + 1];
    }
    if (tid >= NODES && tid < NODES + GPC) {
        int g = tid - NODES;
        sAnc[g] = anchors[graphBase + g];
        sJmp[g] = n_jumps[graphBase + g];
    }
    __syncthreads();

    // ---- distances ----
    for (int idx = tid; idx < NODES * 8; idx += NT) {
        int n = idx >> 3, jj = idx & 7;
        int j = (n & ~7) + jj;
        float dx = sPos[2 * n]     - sPos[2 * j];
        float dy = sPos[2 * n + 1] - sPos[2 * j + 1];
        sD[idx] = sqrtf(dx * dx + dy * dy);
    }

    // ---- pre layer 1 (coalesced gather): warp w -> rows 8w..8w+7, lane -> 4 consecutive cols ----
    // All row pointers are warp-uniform; lanes read consecutive float4 -> 4 wf per LDG.128.
    {
        const float4* b1v = (const float4*)pre_b1;
#pragma unroll
        for (int r = 0; r < 8; ++r) {
            int n = warp * 8 + r;
            int g = n >> 3;
            float px = sPos[2 * n], py = sPos[2 * n + 1];
            const float4* rw0 = (const float4*)(pre_W1);
            const float4* rw1 = (const float4*)(pre_W1 + H);
            const float4* rc  = (const float4*)(pre_W1 + (2 + sCol[n]) * H);
            const float4* rm  = (const float4*)(pre_W1 + (10 + (sMrk[n] - 8)) * H);
            const float4* ra  = (const float4*)(pre_W1 + (18 + sAnc[g]) * H);
            const float4* rj  = (const float4*)(pre_W1 + (34 + sJmp[g]) * H);

            float4 vc = __ldg(&rc[lane]);
            float4 vm = __ldg(&rm[lane]);
            float4 va = __ldg(&ra[lane]);
            float4 vj = __ldg(&rj[lane]);
            float4 vb = __ldg(&b1v[lane]);
            float4 v0 = __ldg(&rw0[lane]);
            float4 v1 = __ldg(&rw1[lane]);

            float4 o;
            o.x = fmaxf(fmaf(px, v0.x, fmaf(py, v1.x, vc.x + vm.x + va.x + vj.x + vb.x)), 0.f);
            o.y = fmaxf(fmaf(px, v0.y, fmaf(py, v1.y, vc.y + vm.y + va.y + vj.y + vb.y)), 0.f);
            o.z = fmaxf(fmaf(px, v0.z, fmaf(py, v1.z, vc.z + vm.z + va.z + vj.z + vb.z)), 0.f);
            o.w = fmaxf(fmaf(px, v0.w, fmaf(py, v1.w, vc.w + vm.w + va.w + vj.w + vb.w)), 0.f);
            *(float4*)&sA[n * AP + 4 * lane] = o;
        }
    }
    __syncthreads();

    // ---- pre layer 2 (linear): x0 = h1 @ pre_W2 + b2 -> sX0 ----
    {
        float acc[2][4][4]; ACC_ZERO(acc);
        gemm_acc(sA, 0, acc);
        gemm_epi(acc, sX0, pre_b2, 1.f, false);
    }
    __syncthreads();

    // ---- A = x0 @ msg_W1[0:128] -> sA ; B = x0 @ msg_W1[128:256] -> sB ----
    {
        float acc[2][4][4]; ACC_ZERO(acc);
        gemm_acc(sX0, 1, acc);
        gemm_epi(acc, sA, nullptr, 0.f, false);
    }
    {
        float acc[2][4][4]; ACC_ZERO(acc);
        gemm_acc(sX0, 2, acc);
        gemm_epi(acc, sB, nullptr, 0.f, false);
    }
    __syncthreads();

    // ---- edge aggregation: s[n] = sum_{j!=n} relu(A[n]+B[j]+d*w1d+b1) -> sA ----
    {
        const float* w1d = msg_W1 + 2 * H * H;
        float wv[8], bv[8];
#pragma unroll
        for (int c = 0; c < 8; ++c) {
            wv[c] = __ldg(&w1d[c0 + c]);
            bv[c] = __ldg(&msg_b1[c0 + c]);
        }
#pragma unroll
        for (int i = 0; i < 4; ++i) {
            int n = r0 + i, nb = n & ~7, nloc = n & 7;
            float a[8];
            {
                float4 a0 = *(const float4*)&sA[n * AP + c0];
                float4 a1 = *(const float4*)&sA[n * AP + c0 + 4];
                a[0]=a0.x; a[1]=a0.y; a[2]=a0.z; a[3]=a0.w; a[4]=a1.x; a[5]=a1.y; a[6]=a1.z; a[7]=a1.w;
            }
            float s[8] = {0,0,0,0,0,0,0,0};
#pragma unroll
            for (int jj = 0; jj < 8; ++jj) {
                if (jj == nloc) continue;
                float d = sD[n * 8 + jj];
                const float* bp = sB + (nb + jj) * AP + c0;
                float4 b0 = *(const float4*)bp;
                float4 b1 = *(const float4*)(bp + 4);
                float bb[8] = {b0.x, b0.y, b0.z, b0.w, b1.x, b1.y, b1.z, b1.w};
#pragma unroll
                for (int c = 0; c < 8; ++c) {
                    float t = a[c] + bb[c] + fmaf(d, wv[c], bv[c]);
                    s[c] += fmaxf(t, 0.f);
                }
            }
            *(float4*)&sA[n * AP + c0]     = make_float4(s[0], s[1], s[2], s[3]);
            *(float4*)&sA[n * AP + c0 + 4] = make_float4(s[4], s[5], s[6], s[7]);
        }
    }
    __syncthreads();

    // ---- upd = s @ msg_W2 + 7*msg_b2 -> sB ----
    {
        float acc[2][4][4]; ACC_ZERO(acc);
        gemm_acc(sA, 3, acc);
        gemm_epi(acc, sB, msg_b2, 7.f, false);
    }
    __syncthreads();

    // ---- post layer 1 (fused 2K): h = relu(upd@P1a + x0@P1b + b1) -> sA ----
    {
        float acc[2][4][4]; ACC_ZERO(acc);
        gemm_acc(sB,  4, acc);
        gemm_acc(sX0, 5, acc);
        gemm_epi(acc, sA, post_b1, 1.f, true);
    }
    __syncthreads();

    // ---- post layer 2: x = h @ post_W2 + b2 -> sB ----
    {
        float acc[2][4][4]; ACC_ZERO(acc);
        gemm_acc(sA, 6, acc);
        gemm_epi(acc, sB, post_b2, 1.f, false);
    }
    __syncthreads();

    // ---- graph sum -> sG ----
    for (int idx = tid; idx < GPC * H; idx += NT) {
        int g = idx >> 7, k = idx & (H - 1);
        float s = 0.f;
#pragma unroll
        for (int i = 0; i < 8; ++i) s += sB[(g * 8 + i) * AP + k];
        sG[g * AP + k] = s;
    }
    __syncthreads();

    // ---- out layer 1 (SIMT): col k=tid fixed per thread ----
    {
        float s0 = __ldg(&out_b1[tid]);
        float s1 = s0, s2 = s0, s3 = s0;
#pragma unroll 4
        for (int kk = 0; kk < H; ++kk) {
            float w = __ldg(&out_W1[kk * H + tid]);
            s0 = fmaf(sG[0 * AP + kk], w, s0);
            s1 = fmaf(sG[1 * AP + kk], w, s1);
            s2 = fmaf(sG[2 * AP + kk], w, s2);
            s3 = fmaf(sG[3 * AP + kk], w, s3);
        }
        sB[0 * AP + tid] = fmaxf(s0, 0.f);
        sB[1 * AP + tid] = fmaxf(s1, 0.f);
        sB[2 * AP + tid] = fmaxf(s2, 0.f);
        sB[3 * AP + tid] = fmaxf(s3, 0.f);
    }
    __syncthreads();

    // ---- out layer 2 (SIMT): logits -> gmem ----
    if (tid < GPC * 16) {
        int g = tid >> 4, o = tid & 15;
        float s = __ldg(&out_b2[o]);
#pragma unroll 8
        for (int k = 0; k < H; ++k)
            s = fmaf(sB[g * AP + k], __ldg(&out_W2[k * 16 + o]), s);
        out[(graphBase + g) * 16 + o] = s;
    }
}

extern "C" void kernel_launch(void* const* d_in, const int* in_sizes, int n_in,
                              void* d_out, int out_size)
{
    const int*   anchors   = (const int*)d_in[0];
    const int*   n_jumps   = (const int*)d_in[1];
    const float* positions = (const float*)d_in[2];
    const int*   colors    = (const int*)d_in[3];
    const int*   markers   = (const int*)d_in[4];
    const float* pre_W1  = (const float*)d_in[5];
    const float* pre_b1  = (const float*)d_in[6];
    const float* pre_W2  = (const float*)d_in[7];
    const float* pre_b2  = (const float*)d_in[8];
    const float* msg_W1  = (const float*)d_in[9];
    const float* msg_b1  = (const float*)d_in[10];
    const float* msg_W2  = (const float*)d_in[11];
    const float* msg_b2  = (const float*)d_in[12];
    const float* post_W1 = (const float*)d_in[13];
    const float* post_b1 = (const float*)d_in[14];
    const float* post_W2 = (const float*)d_in[15];
    const float* post_b2 = (const float*)d_in[16];
    const float* out_W1  = (const float*)d_in[17];
    const float* out_b1  = (const float*)d_in[18];
    const float* out_W2  = (const float*)d_in[19];
    const float* out_b2  = (const float*)d_in[20];

    // 1) pack + pre-split weights (same every call: deterministic, graph-capturable)
    int prepThreads = NMAT * MAT_ENTRIES;
    prep_weights_kernel<<<(prepThreads + 255) / 256, 256>>>(
        pre_W2, msg_W1, msg_W2, post_W1, post_W2);

    // 2) main fused kernel
    int bs = in_sizes[0];
    int blocks = bs / GPC;
    size_t smemBytes = SMEM_FLOATS * sizeof(float);
    cudaFuncSetAttribute(prettyrnn_kernel,
                         cudaFuncAttributeMaxDynamicSharedMemorySize, (int)smemBytes);
    prettyrnn_kernel<<<blocks, NT, smemBytes>>>(
        anchors, n_jumps, positions, colors, markers,
        pre_W1, pre_b1, pre_b2,
        msg_W1, msg_b1, msg_b2,
        post_b1, post_b2,
        out_W1, out_b1, out_W2, out_b2,
        (float*)d_out);
}